// round 11
// baseline (speedup 1.0000x reference)
#include <cuda_runtime.h>
#include <cuda_fp16.h>
#include <math.h>
#include <stdint.h>

#define NTOK 2048
#define DDIM 1024
#define FDIM 4096
#define NEXP 8
#define NLAY 6
#define RTOT (NTOK*2)
#define MAXF 256
#define TAU  2e-4f

// ---------------- scratch ----------------
__device__ float g_xn[NTOK*DDIM];
__device__ float g_probs[NTOK*NEXP];
__device__ int   g_topi[RTOT];
__device__ float g_topv[RTOT];
__device__ int   g_cnt[NEXP], g_off[NEXP];
__device__ int   g_row_tok[RTOT];
__device__ int   g_tok_row[RTOT];
__device__ float g_H[(size_t)RTOT*FDIM];
__device__ float g_Y[(size_t)RTOT*DDIM];
__device__ float g_loss;
// exact-recompute scratch
__device__ int   g_flag[NTOK];
__device__ int   g_flist[MAXF];
__device__ int   g_F;
__device__ float ex_x [MAXF*DDIM];
__device__ float ex_xn[MAXF*DDIM];
__device__ float ex_h [(size_t)MAXF*2*FDIM];
__device__ float ex_y [(size_t)MAXF*2*DDIM];
__device__ int   ex_topi[MAXF*2];
__device__ float ex_topv[MAXF*2];
__device__ int   ex_ecnt[NEXP];
__device__ int   ex_elist[NEXP*2*MAXF];

__device__ __forceinline__ void mma16(float* d, const uint32_t* a, uint32_t b0, uint32_t b1){
    asm volatile("mma.sync.aligned.m16n8k16.row.col.f32.f16.f16.f32 "
        "{%0,%1,%2,%3}, {%4,%5,%6,%7}, {%8,%9}, {%0,%1,%2,%3};"
        : "+f"(d[0]), "+f"(d[1]), "+f"(d[2]), "+f"(d[3])
        : "r"(a[0]), "r"(a[1]), "r"(a[2]), "r"(a[3]), "r"(b0), "r"(b1));
}
// split two floats into (hi half2, lo half2): hi = rn(x); lo = rn(x - hi)
__device__ __forceinline__ void split2(float x, float y, uint32_t& hi, uint32_t& lo){
    __half2 h = __floats2half2_rn(x, y);
    float hx = __low2float(h), hy = __high2float(h);
    __half2 l = __floats2half2_rn(x - hx, y - hy);
    hi = *reinterpret_cast<uint32_t*>(&h);
    lo = *reinterpret_cast<uint32_t*>(&l);
}
__device__ __forceinline__ float gelu_tanh(float x){
    float x3 = x*x*x;
    float t  = tanhf(0.7978845608028654f*(x + 0.044715f*x3));
    return 0.5f*x*(1.0f+t);
}

// ---------------- init ----------------
__global__ void init_kernel(const float* __restrict__ x, float* __restrict__ out){
    int i = blockIdx.x*blockDim.x + threadIdx.x;
    out[i] = x[i];
    if (i < NTOK) g_flag[i] = 0;
    if (i == 0){ g_loss = 0.0f; g_F = 0; }
}

// ---------------- fused LN + router (fast path, with margin flag) ----------------
__global__ void lnrouter_kernel(const float* __restrict__ xin, const float* __restrict__ wr){
    int t = blockIdx.x, tid = threadIdx.x;
    __shared__ float red[256];
    __shared__ float sx[DDIM];
    __shared__ float slog[NEXP];
    float v[4];
    #pragma unroll
    for (int q=0;q<4;q++) v[q] = xin[(size_t)t*DDIM + q*256 + tid];
    float s = v[0]+v[1]+v[2]+v[3];
    red[tid]=s; __syncthreads();
    for (int o=128;o>0;o>>=1){ if(tid<o) red[tid]+=red[tid+o]; __syncthreads(); }
    float mean = red[0]*(1.0f/DDIM);
    __syncthreads();
    float s2=0.f;
    #pragma unroll
    for (int q=0;q<4;q++){ v[q]-=mean; s2 += v[q]*v[q]; }
    red[tid]=s2; __syncthreads();
    for (int o=128;o>0;o>>=1){ if(tid<o) red[tid]+=red[tid+o]; __syncthreads(); }
    float inv = 1.0f/sqrtf(red[0]*(1.0f/DDIM) + 1e-5f);
    #pragma unroll
    for (int q=0;q<4;q++){
        float nv = v[q]*inv;
        g_xn[(size_t)t*DDIM + q*256 + tid] = nv;
        sx[q*256 + tid] = nv;
    }
    __syncthreads();
    int e = tid>>5, lane = tid&31;
    float acc = 0.f;
    for (int d=lane; d<DDIM; d+=32) acc += sx[d]*wr[d*NEXP+e];
    #pragma unroll
    for (int o=16;o>0;o>>=1) acc += __shfl_down_sync(0xffffffffu, acc, o);
    if (lane==0) slog[e]=acc;
    __syncthreads();
    if (tid==0){
        float p[NEXP];
        float m = slog[0];
        #pragma unroll
        for (int i=1;i<NEXP;i++) m = fmaxf(m, slog[i]);
        float ssum = 0.f;
        #pragma unroll
        for (int i=0;i<NEXP;i++){ p[i]=expf(slog[i]-m); ssum+=p[i]; }
        #pragma unroll
        for (int i=0;i<NEXP;i++){ p[i] = p[i]/ssum; g_probs[t*NEXP+i]=p[i]; }
        int i1=0; float v1=p[0];
        #pragma unroll
        for (int i=1;i<NEXP;i++) if (p[i]>v1){ v1=p[i]; i1=i; }
        int i2=-1; float v2=-1e30f;
        #pragma unroll
        for (int i=0;i<NEXP;i++) if (i!=i1 && p[i]>v2){ v2=p[i]; i2=i; }
        float v3=-1e30f;
        #pragma unroll
        for (int i=0;i<NEXP;i++) if (i!=i1 && i!=i2 && p[i]>v3) v3=p[i];
        if (v2 - v3 < TAU) g_flag[t] = 1;
        g_topi[t*2+0]=i1; g_topv[t*2+0]=v1;
        g_topi[t*2+1]=i2; g_topv[t*2+1]=v2;
    }
}

// ---------------- stats + placement (single block) ----------------
__global__ void statsplace_kernel(){
    int tid = threadIdx.x;                 // 1024 threads
    __shared__ int   sc[NEXP];
    __shared__ int   scur[NEXP];
    __shared__ int   soff[NEXP];
    __shared__ float red[1024];
    __shared__ float sexp[NEXP];
    if (tid<NEXP){ sc[tid]=0; scur[tid]=0; }
    __syncthreads();
    for (int i=tid;i<RTOT;i+=1024) atomicAdd(&sc[g_topi[i]], 1);
    float myp[NEXP];
    #pragma unroll
    for (int e=0;e<NEXP;e++) myp[e]=0.f;
    for (int t=tid;t<NTOK;t+=1024){
        #pragma unroll
        for (int e=0;e<NEXP;e++) myp[e] += g_probs[t*NEXP+e];
    }
    __syncthreads();
    for (int e=0;e<NEXP;e++){
        red[tid]=myp[e]; __syncthreads();
        for (int o=512;o>0;o>>=1){ if(tid<o) red[tid]+=red[tid+o]; __syncthreads(); }
        if (tid==0) sexp[e]=red[0];
        __syncthreads();
    }
    if (tid==0){
        float loss=0.f; int off=0;
        #pragma unroll
        for (int e=0;e<NEXP;e++){
            loss += ((float)sc[e]*(1.0f/NTOK)) * (sexp[e]*(1.0f/NTOK));
            g_cnt[e]=sc[e]; g_off[e]=off; soff[e]=off; off+=sc[e];
        }
        g_loss += (float)NEXP*loss;
    }
    __syncthreads();
    for (int i=tid;i<RTOT;i+=1024){
        int e = g_topi[i];
        int r = soff[e] + atomicAdd(&scur[e], 1);
        g_row_tok[r] = i>>1;
        g_tok_row[i] = r;
    }
}

// ---------------- fp16x3 mma.sync grouped GEMM ----------------
#define APAD2 12
#define BPAD2 17
#define OFF_AH 0
#define OFF_AL 6144
#define OFF_BH 12288
#define OFF_BL 20992
#define BUF_SZ 29696
#define SM_TOTAL (512 + 2*BUF_SZ)

template<bool G1, int OCC>
__global__ void __launch_bounds__(256, OCC) moe_gemm_h3(const float* __restrict__ W,
                                                        const float* __restrict__ bias){
    constexpr int LDA = G1 ? DDIM : FDIM;
    constexpr int KT  = G1 ? DDIM : FDIM;
    constexpr int LDW = G1 ? FDIM : DDIM;
    constexpr int S   = KT/16;

    extern __shared__ char smem[];
    int* sidx = (int*)smem;
    char* bufbase = smem + 512;

    int e = blockIdx.z;
    int cnt = g_cnt[e];
    int m0 = blockIdx.y*128;
    if (m0 >= cnt) return;
    int off = g_off[e];
    int n0 = blockIdx.x*128;
    int tid = threadIdx.x, w = tid>>5, lane = tid&31;
    int g = lane>>2, tig = lane&3;
    int mw = (w&1)*64, nw = (w>>1)*32;

    const float* Asrc = G1 ? g_xn : g_H;
    float*       Out  = G1 ? g_H  : g_Y;

    if (tid < 128){
        int i = m0 + tid; if (i >= cnt) i = cnt-1;
        sidx[tid] = G1 ? g_row_tok[off+i] : (off+i);
    }
    __syncthreads();

    const float* aptr0 = Asrc + (size_t)sidx[tid>>2]*LDA + (tid&3)*4;
    const float* aptr1 = Asrc + (size_t)sidx[(tid>>2)+64]*LDA + (tid&3)*4;
    int kp = tid>>6;
    int n2 = (tid&63)*2;
    const float* bptr = W + (size_t)e*KT*LDW + n0 + n2;
    const float* biasp = bias + (size_t)e*LDW + n0;

    float4 av[2];
    float2 q00, q01, q10, q11;
    auto LOADS = [&](int s){
        int k0 = s*16;
        av[0] = *(const float4*)(aptr0 + k0);
        av[1] = *(const float4*)(aptr1 + k0);
        q00 = *(const float2*)(bptr + (size_t)(k0 + 2*kp    )*LDW);
        q01 = *(const float2*)(bptr + (size_t)(k0 + 2*kp + 1)*LDW);
        q10 = *(const float2*)(bptr + (size_t)(k0 + 2*kp + 8)*LDW);
        q11 = *(const float2*)(bptr + (size_t)(k0 + 2*kp + 9)*LDW);
    };
    auto STORES = [&](int b){
        char* bb = bufbase + b*BUF_SZ;
        uint32_t* Ah = (uint32_t*)(bb + OFF_AH);
        uint32_t* Al = (uint32_t*)(bb + OFF_AL);
        uint32_t* Bh = (uint32_t*)(bb + OFF_BH);
        uint32_t* Bl = (uint32_t*)(bb + OFF_BL);
        int kq = tid&3;
        #pragma unroll
        for (int i=0;i<2;i++){
            int row = (tid>>2) + 64*i;
            uint32_t h01,l01,h23,l23;
            split2(av[i].x, av[i].y, h01, l01);
            split2(av[i].z, av[i].w, h23, l23);
            int a = row*APAD2 + kq*2;
            *(uint2*)(Ah + a) = make_uint2(h01, h23);
            *(uint2*)(Al + a) = make_uint2(l01, l23);
        }
        {
            uint32_t h,l;
            split2(q00.x, q01.x, h, l); Bh[ n2   *BPAD2 + kp    ] = h; Bl[ n2   *BPAD2 + kp    ] = l;
            split2(q00.y, q01.y, h, l); Bh[(n2+1)*BPAD2 + kp    ] = h; Bl[(n2+1)*BPAD2 + kp    ] = l;
            split2(q10.x, q11.x, h, l); Bh[ n2   *BPAD2 + kp + 4] = h; Bl[ n2   *BPAD2 + kp + 4] = l;
            split2(q10.y, q11.y, h, l); Bh[(n2+1)*BPAD2 + kp + 4] = h; Bl[(n2+1)*BPAD2 + kp + 4] = l;
        }
    };

    float acc[4][4][4] = {};
    auto COMPUTE = [&](int b){
        char* bb = bufbase + b*BUF_SZ;
        const uint32_t* Ah = (const uint32_t*)(bb + OFF_AH);
        const uint32_t* Al = (const uint32_t*)(bb + OFF_AL);
        const uint32_t* Bh = (const uint32_t*)(bb + OFF_BH);
        const uint32_t* Bl = (const uint32_t*)(bb + OFF_BL);
        uint32_t afh[4][4], afl[4][4];
        #pragma unroll
        for (int mf=0;mf<4;mf++){
            int r0 = mw + mf*16 + g, r1 = r0 + 8;
            afh[mf][0] = Ah[r0*APAD2 + tig];
            afh[mf][1] = Ah[r1*APAD2 + tig];
            afh[mf][2] = Ah[r0*APAD2 + tig + 4];
            afh[mf][3] = Ah[r1*APAD2 + tig + 4];
            afl[mf][0] = Al[r0*APAD2 + tig];
            afl[mf][1] = Al[r1*APAD2 + tig];
            afl[mf][2] = Al[r0*APAD2 + tig + 4];
            afl[mf][3] = Al[r1*APAD2 + tig + 4];
        }
        #pragma unroll
        for (int nf=0;nf<4;nf++){
            int n = nw + nf*8 + g;
            uint32_t bh0 = Bh[n*BPAD2 + tig];
            uint32_t bh1 = Bh[n*BPAD2 + tig + 4];
            uint32_t bl0 = Bl[n*BPAD2 + tig];
            uint32_t bl1 = Bl[n*BPAD2 + tig + 4];
            #pragma unroll
            for (int mf=0;mf<4;mf++){
                mma16(acc[mf][nf], afh[mf], bh0, bh1);   // hi*hi
                mma16(acc[mf][nf], afl[mf], bh0, bh1);   // lo*hi
                mma16(acc[mf][nf], afh[mf], bl0, bl1);   // hi*lo
            }
        }
    };

    LOADS(0);
    STORES(0);
    __syncthreads();
    for (int s=0;s<S;s++){
        if (s+1 < S) LOADS(s+1);
        COMPUTE(s&1);
        if (s+1 < S){
            STORES((s+1)&1);
            __syncthreads();
        }
    }

    #pragma unroll
    for (int mf=0;mf<4;mf++){
        int r0 = m0 + mw + mf*16 + g;
        int r1 = r0 + 8;
        #pragma unroll
        for (int nf=0;nf<4;nf++){
            int col = nw + nf*8 + tig*2;
            float b0 = biasp[col], b1 = biasp[col+1];
            if (r0 < cnt){
                float2 o;
                o.x = acc[mf][nf][0] + b0;
                o.y = acc[mf][nf][1] + b1;
                if (G1){ o.x = gelu_tanh(o.x); o.y = gelu_tanh(o.y); }
                *(float2*)(Out + (size_t)(off+r0)*LDW + n0 + col) = o;
            }
            if (r1 < cnt){
                float2 o;
                o.x = acc[mf][nf][2] + b0;
                o.y = acc[mf][nf][3] + b1;
                if (G1){ o.x = gelu_tanh(o.x); o.y = gelu_tanh(o.y); }
                *(float2*)(Out + (size_t)(off+r1)*LDW + n0 + col) = o;
            }
        }
    }
}

// ---------------- combine ----------------
__global__ void combine_kernel(float* __restrict__ out){
    int t = blockIdx.x, tid = threadIdx.x;
    int r1 = g_tok_row[t*2+0], r2 = g_tok_row[t*2+1];
    float g1 = g_topv[t*2+0],  g2 = g_topv[t*2+1];
    const float* y1 = g_Y + (size_t)r1*DDIM;
    const float* y2 = g_Y + (size_t)r2*DDIM;
    #pragma unroll
    for (int q=0;q<4;q++){
        int d = q*256 + tid;
        out[(size_t)t*DDIM + d] += g1*y1[d] + g2*y2[d];
    }
}
__global__ void finish_kernel(float* __restrict__ out){
    out[(size_t)NTOK*DDIM] = g_loss;
}

// ================= exact-recompute path (bitwise-R1 for flagged tokens) =================
__global__ void flist_kernel(){
    int t = blockIdx.x*blockDim.x + threadIdx.x;
    if (t < NTOK && g_flag[t]){
        int pos = atomicAdd(&g_F, 1);
        if (pos < MAXF) g_flist[pos] = t;
    }
}
__global__ void ex_init_kernel(const float* __restrict__ x){
    int b = blockIdx.x;
    if (b >= g_F || b >= MAXF) return;
    int t = g_flist[b], tid = threadIdx.x;
    #pragma unroll
    for (int q=0;q<4;q++)
        ex_x[b*DDIM + q*256 + tid] = x[(size_t)t*DDIM + q*256 + tid];
}
__global__ void ex_ln_kernel(){
    int b = blockIdx.x;
    if (b >= g_F || b >= MAXF) return;
    int tid = threadIdx.x;
    __shared__ float red[256];
    float v[4];
    #pragma unroll
    for (int q=0;q<4;q++) v[q] = ex_x[b*DDIM + q*256 + tid];
    float s = v[0]+v[1]+v[2]+v[3];
    red[tid]=s; __syncthreads();
    for (int o=128;o>0;o>>=1){ if(tid<o) red[tid]+=red[tid+o]; __syncthreads(); }
    float mean = red[0]*(1.0f/DDIM);
    __syncthreads();
    float s2=0.f;
    #pragma unroll
    for (int q=0;q<4;q++){ v[q]-=mean; s2 += v[q]*v[q]; }
    red[tid]=s2; __syncthreads();
    for (int o=128;o>0;o>>=1){ if(tid<o) red[tid]+=red[tid+o]; __syncthreads(); }
    float inv = 1.0f/sqrtf(red[0]*(1.0f/DDIM) + 1e-5f);
    #pragma unroll
    for (int q=0;q<4;q++) ex_xn[b*DDIM + q*256 + tid] = v[q]*inv;
}
__global__ void ex_router_kernel(const float* __restrict__ wr){
    int b = blockIdx.x;
    if (b >= g_F || b >= MAXF) return;
    int tid = threadIdx.x;
    __shared__ float sx[DDIM];
    __shared__ float slog[NEXP];
    #pragma unroll
    for (int q=0;q<4;q++) sx[q*256+tid] = ex_xn[b*DDIM + q*256 + tid];
    __syncthreads();
    int e = tid>>5, lane = tid&31;
    float acc = 0.f;
    for (int d=lane; d<DDIM; d+=32) acc += sx[d]*wr[d*NEXP+e];
    #pragma unroll
    for (int o=16;o>0;o>>=1) acc += __shfl_down_sync(0xffffffffu, acc, o);
    if (lane==0) slog[e]=acc;
    __syncthreads();
    if (tid==0){
        float p[NEXP];
        float m = slog[0];
        #pragma unroll
        for (int i=1;i<NEXP;i++) m = fmaxf(m, slog[i]);
        float ssum = 0.f;
        #pragma unroll
        for (int i=0;i<NEXP;i++){ p[i]=expf(slog[i]-m); ssum+=p[i]; }
        #pragma unroll
        for (int i=0;i<NEXP;i++) p[i] = p[i]/ssum;
        int i1=0; float v1=p[0];
        #pragma unroll
        for (int i=1;i<NEXP;i++) if (p[i]>v1){ v1=p[i]; i1=i; }
        int i2=-1; float v2=-1e30f;
        #pragma unroll
        for (int i=0;i<NEXP;i++) if (i!=i1 && p[i]>v2){ v2=p[i]; i2=i; }
        ex_topi[b*2+0]=i1; ex_topv[b*2+0]=v1;
        ex_topi[b*2+1]=i2; ex_topv[b*2+1]=v2;
    }
}
// group flagged slots by expert (order within expert irrelevant: slots independent)
__global__ void ex_group_kernel(){
    int tid = threadIdx.x;
    if (tid < NEXP) ex_ecnt[tid] = 0;
    __syncthreads();
    int F = g_F; if (F > MAXF) F = MAXF;
    for (int s = tid; s < 2*F; s += 256){
        int e = ex_topi[s];
        int p = atomicAdd(&ex_ecnt[e], 1);
        ex_elist[e*(2*MAXF) + p] = s;
    }
}
// exact GEMM1, expert-grouped: grid (FDIM/256, NEXP).
// Each weight LDG serves up to 8 token fmaf chains (ascending-k, bitwise == before).
__global__ void __launch_bounds__(256) ex_gemm1_kernel(const float* __restrict__ w1l,
                                                       const float* __restrict__ b1l){
    int e = blockIdx.y;
    int cnt = ex_ecnt[e];
    if (cnt == 0) return;
    int tid = threadIdx.x;
    int col = blockIdx.x*256 + tid;
    __shared__ float sx[8*DDIM];          // 32 KB
    __shared__ int   sslot[8];
    const float* wcol = w1l + (size_t)e*DDIM*FDIM + col;
    float bb = b1l[(size_t)e*FDIM + col];

    for (int c0 = 0; c0 < cnt; c0 += 8){
        int C = cnt - c0; if (C > 8) C = 8;
        __syncthreads();
        if (tid < 8 && tid < C) sslot[tid] = ex_elist[e*(2*MAXF) + c0 + tid];
        __syncthreads();
        for (int j = 0; j < C; j++){
            int b = sslot[j] >> 1;
            #pragma unroll
            for (int q=0;q<4;q++) sx[j*DDIM + q*256 + tid] = ex_xn[b*DDIM + q*256 + tid];
        }
        __syncthreads();
        float acc[8] = {};
        #pragma unroll 4
        for (int k=0;k<DDIM;k++){
            float wv = wcol[(size_t)k*FDIM];
            #pragma unroll
            for (int j=0;j<8;j++) acc[j] = fmaf(sx[j*DDIM + k], wv, acc[j]);
        }
        for (int j = 0; j < C; j++)
            ex_h[(size_t)sslot[j]*FDIM + col] = gelu_tanh(acc[j] + bb);
    }
}
// exact GEMM2, expert-grouped + k-tiled (4 chunks of 1024): grid (DDIM/256, NEXP)
__global__ void __launch_bounds__(256) ex_gemm2_kernel(const float* __restrict__ w2l,
                                                       const float* __restrict__ b2l){
    int e = blockIdx.y;
    int cnt = ex_ecnt[e];
    if (cnt == 0) return;
    int tid = threadIdx.x;
    int col = blockIdx.x*256 + tid;
    __shared__ float sh[8*1024];          // 32 KB (k-chunk of 8 rows)
    __shared__ int   sslot[8];
    const float* wcol = w2l + (size_t)e*FDIM*DDIM + col;
    float bb = b2l[(size_t)e*DDIM + col];

    for (int c0 = 0; c0 < cnt; c0 += 8){
        int C = cnt - c0; if (C > 8) C = 8;
        __syncthreads();
        if (tid < 8 && tid < C) sslot[tid] = ex_elist[e*(2*MAXF) + c0 + tid];
        __syncthreads();
        float acc[8] = {};
        for (int kc = 0; kc < 4; kc++){
            __syncthreads();
            for (int j = 0; j < C; j++){
                int slot = sslot[j];
                #pragma unroll
                for (int q=0;q<4;q++)
                    sh[j*1024 + q*256 + tid] = ex_h[(size_t)slot*FDIM + kc*1024 + q*256 + tid];
            }
            __syncthreads();
            int kbase = kc*1024;
            #pragma unroll 4
            for (int k=0;k<1024;k++){
                float wv = wcol[(size_t)(kbase + k)*DDIM];
                #pragma unroll
                for (int j=0;j<8;j++) acc[j] = fmaf(sh[j*1024 + k], wv, acc[j]);
            }
        }
        for (int j = 0; j < C; j++)
            ex_y[(size_t)sslot[j]*DDIM + col] = acc[j] + bb;
    }
}
__global__ void ex_combine_kernel(){
    int b = blockIdx.x;
    if (b >= g_F || b >= MAXF) return;
    int tid = threadIdx.x;
    float g1 = ex_topv[b*2+0], g2 = ex_topv[b*2+1];
    const float* y1 = ex_y + ((size_t)b*2+0)*DDIM;
    const float* y2 = ex_y + ((size_t)b*2+1)*DDIM;
    #pragma unroll
    for (int q=0;q<4;q++){
        int d = q*256 + tid;
        ex_x[b*DDIM + d] += g1*y1[d] + g2*y2[d];
    }
}
__global__ void ex_write_kernel(float* __restrict__ out){
    int b = blockIdx.x;
    if (b >= g_F || b >= MAXF) return;
    int t = g_flist[b], tid = threadIdx.x;
    #pragma unroll
    for (int q=0;q<4;q++)
        out[(size_t)t*DDIM + q*256 + tid] = ex_x[b*DDIM + q*256 + tid];
}

// ---------------- launch ----------------
extern "C" void kernel_launch(void* const* d_in, const int* in_sizes, int n_in,
                              void* d_out, int out_size){
    const float* x  = (const float*)d_in[0];
    const float* wr = (const float*)d_in[1];
    const float* w1 = (const float*)d_in[2];
    const float* b1 = (const float*)d_in[3];
    const float* w2 = (const float*)d_in[4];
    const float* b2 = (const float*)d_in[5];
    float* out = (float*)d_out;

    cudaFuncSetAttribute((const void*)moe_gemm_h3<true,2>,  cudaFuncAttributeMaxDynamicSharedMemorySize, SM_TOTAL);
    cudaFuncSetAttribute((const void*)moe_gemm_h3<false,1>, cudaFuncAttributeMaxDynamicSharedMemorySize, SM_TOTAL);

    init_kernel<<<NTOK, 1024>>>(x, out);

    // fast path (launch #4 == moe_gemm_h3<true,2> for ncu capture)
    for (int l=0;l<NLAY;l++){
        const float* wr_l = wr + (size_t)l*DDIM*NEXP;
        const float* w1_l = w1 + (size_t)l*NEXP*DDIM*FDIM;
        const float* b1_l = b1 + (size_t)l*NEXP*FDIM;
        const float* w2_l = w2 + (size_t)l*NEXP*FDIM*DDIM;
        const float* b2_l = b2 + (size_t)l*NEXP*DDIM;

        lnrouter_kernel  <<<NTOK, 256>>>(out, wr_l);
        statsplace_kernel<<<1, 1024>>>();
        moe_gemm_h3<true,2> <<<dim3(FDIM/128, 32, NEXP), 256, SM_TOTAL>>>(w1_l, b1_l);
        moe_gemm_h3<false,1><<<dim3(DDIM/128, 32, NEXP), 256, SM_TOTAL>>>(w2_l, b2_l);
        combine_kernel<<<NTOK, 256>>>(out);
    }

    // exact recompute of flagged tokens (bitwise-R1, expert-grouped)
    flist_kernel  <<<NTOK/256, 256>>>();
    ex_init_kernel<<<MAXF, 256>>>(x);
    for (int l=0;l<NLAY;l++){
        const float* wr_l = wr + (size_t)l*DDIM*NEXP;
        const float* w1_l = w1 + (size_t)l*NEXP*DDIM*FDIM;
        const float* b1_l = b1 + (size_t)l*NEXP*FDIM;
        const float* w2_l = w2 + (size_t)l*NEXP*FDIM*DDIM;
        const float* b2_l = b2 + (size_t)l*NEXP*DDIM;

        ex_ln_kernel    <<<MAXF, 256>>>();
        ex_router_kernel<<<MAXF, 256>>>(wr_l);
        ex_group_kernel <<<1, 256>>>();
        ex_gemm1_kernel <<<dim3(FDIM/256, NEXP), 256>>>(w1_l, b1_l);
        ex_gemm2_kernel <<<dim3(DDIM/256, NEXP), 256>>>(w2_l, b2_l);
        ex_combine_kernel<<<MAXF, 256>>>();
    }
    ex_write_kernel<<<MAXF, 256>>>(out);

    if (out_size > NTOK*DDIM) finish_kernel<<<1,1>>>(out);
}

// round 12
// speedup vs baseline: 2.2889x; 2.2889x over previous
#include <cuda_runtime.h>
#include <cuda_fp16.h>
#include <math.h>
#include <stdint.h>

#define NTOK 2048
#define DDIM 1024
#define FDIM 4096
#define NEXP 8
#define NLAY 6
#define RTOT (NTOK*2)
#define MAXF 256
#define TAU  2e-4f

// ---------------- scratch ----------------
__device__ float g_xn[NTOK*DDIM];
__device__ float g_probs[NTOK*NEXP];
__device__ int   g_topi[RTOT];
__device__ float g_topv[RTOT];
__device__ int   g_cnt[NEXP], g_off[NEXP];
__device__ int   g_row_tok[RTOT];
__device__ int   g_tok_row[RTOT];
__device__ float g_H[(size_t)RTOT*FDIM];
__device__ float g_Y[(size_t)RTOT*DDIM];
__device__ float g_loss;
// exact-recompute scratch
__device__ int   g_flag[NTOK];
__device__ int   g_flist[MAXF];
__device__ int   g_F;
__device__ float ex_x [MAXF*DDIM];
__device__ float ex_xn[MAXF*DDIM];
__device__ float ex_h [(size_t)MAXF*2*FDIM];
__device__ float ex_y [(size_t)MAXF*2*DDIM];
__device__ int   ex_topi[MAXF*2];
__device__ float ex_topv[MAXF*2];

__device__ __forceinline__ void mma16(float* d, const uint32_t* a, uint32_t b0, uint32_t b1){
    asm volatile("mma.sync.aligned.m16n8k16.row.col.f32.f16.f16.f32 "
        "{%0,%1,%2,%3}, {%4,%5,%6,%7}, {%8,%9}, {%0,%1,%2,%3};"
        : "+f"(d[0]), "+f"(d[1]), "+f"(d[2]), "+f"(d[3])
        : "r"(a[0]), "r"(a[1]), "r"(a[2]), "r"(a[3]), "r"(b0), "r"(b1));
}
// split two floats into (hi half2, lo half2): hi = rn(x); lo = rn(x - hi)
__device__ __forceinline__ void split2(float x, float y, uint32_t& hi, uint32_t& lo){
    __half2 h = __floats2half2_rn(x, y);
    float hx = __low2float(h), hy = __high2float(h);
    __half2 l = __floats2half2_rn(x - hx, y - hy);
    hi = *reinterpret_cast<uint32_t*>(&h);
    lo = *reinterpret_cast<uint32_t*>(&l);
}
__device__ __forceinline__ float gelu_tanh(float x){
    float x3 = x*x*x;
    float t  = tanhf(0.7978845608028654f*(x + 0.044715f*x3));
    return 0.5f*x*(1.0f+t);
}

// ---------------- init ----------------
__global__ void init_kernel(const float* __restrict__ x, float* __restrict__ out){
    int i = blockIdx.x*blockDim.x + threadIdx.x;
    out[i] = x[i];
    if (i < NTOK) g_flag[i] = 0;
    if (i == 0){ g_loss = 0.0f; g_F = 0; }
}

// ---------------- fused LN + router (fast path, with margin flag) ----------------
__global__ void lnrouter_kernel(const float* __restrict__ xin, const float* __restrict__ wr){
    int t = blockIdx.x, tid = threadIdx.x;
    __shared__ float red[256];
    __shared__ float sx[DDIM];
    __shared__ float slog[NEXP];
    float v[4];
    #pragma unroll
    for (int q=0;q<4;q++) v[q] = xin[(size_t)t*DDIM + q*256 + tid];
    float s = v[0]+v[1]+v[2]+v[3];
    red[tid]=s; __syncthreads();
    for (int o=128;o>0;o>>=1){ if(tid<o) red[tid]+=red[tid+o]; __syncthreads(); }
    float mean = red[0]*(1.0f/DDIM);
    __syncthreads();
    float s2=0.f;
    #pragma unroll
    for (int q=0;q<4;q++){ v[q]-=mean; s2 += v[q]*v[q]; }
    red[tid]=s2; __syncthreads();
    for (int o=128;o>0;o>>=1){ if(tid<o) red[tid]+=red[tid+o]; __syncthreads(); }
    float inv = 1.0f/sqrtf(red[0]*(1.0f/DDIM) + 1e-5f);
    #pragma unroll
    for (int q=0;q<4;q++){
        float nv = v[q]*inv;
        g_xn[(size_t)t*DDIM + q*256 + tid] = nv;
        sx[q*256 + tid] = nv;
    }
    __syncthreads();
    int e = tid>>5, lane = tid&31;
    float acc = 0.f;
    for (int d=lane; d<DDIM; d+=32) acc += sx[d]*wr[d*NEXP+e];
    #pragma unroll
    for (int o=16;o>0;o>>=1) acc += __shfl_down_sync(0xffffffffu, acc, o);
    if (lane==0) slog[e]=acc;
    __syncthreads();
    if (tid==0){
        float p[NEXP];
        float m = slog[0];
        #pragma unroll
        for (int i=1;i<NEXP;i++) m = fmaxf(m, slog[i]);
        float ssum = 0.f;
        #pragma unroll
        for (int i=0;i<NEXP;i++){ p[i]=expf(slog[i]-m); ssum+=p[i]; }
        #pragma unroll
        for (int i=0;i<NEXP;i++){ p[i] = p[i]/ssum; g_probs[t*NEXP+i]=p[i]; }
        int i1=0; float v1=p[0];
        #pragma unroll
        for (int i=1;i<NEXP;i++) if (p[i]>v1){ v1=p[i]; i1=i; }
        int i2=-1; float v2=-1e30f;
        #pragma unroll
        for (int i=0;i<NEXP;i++) if (i!=i1 && p[i]>v2){ v2=p[i]; i2=i; }
        float v3=-1e30f;
        #pragma unroll
        for (int i=0;i<NEXP;i++) if (i!=i1 && i!=i2 && p[i]>v3) v3=p[i];
        if (v2 - v3 < TAU) g_flag[t] = 1;
        g_topi[t*2+0]=i1; g_topv[t*2+0]=v1;
        g_topi[t*2+1]=i2; g_topv[t*2+1]=v2;
    }
}

// ---------------- stats + placement (single block) ----------------
__global__ void statsplace_kernel(){
    int tid = threadIdx.x;                 // 1024 threads
    __shared__ int   sc[NEXP];
    __shared__ int   scur[NEXP];
    __shared__ int   soff[NEXP];
    __shared__ float red[1024];
    __shared__ float sexp[NEXP];
    if (tid<NEXP){ sc[tid]=0; scur[tid]=0; }
    __syncthreads();
    for (int i=tid;i<RTOT;i+=1024) atomicAdd(&sc[g_topi[i]], 1);
    float myp[NEXP];
    #pragma unroll
    for (int e=0;e<NEXP;e++) myp[e]=0.f;
    for (int t=tid;t<NTOK;t+=1024){
        #pragma unroll
        for (int e=0;e<NEXP;e++) myp[e] += g_probs[t*NEXP+e];
    }
    __syncthreads();
    for (int e=0;e<NEXP;e++){
        red[tid]=myp[e]; __syncthreads();
        for (int o=512;o>0;o>>=1){ if(tid<o) red[tid]+=red[tid+o]; __syncthreads(); }
        if (tid==0) sexp[e]=red[0];
        __syncthreads();
    }
    if (tid==0){
        float loss=0.f; int off=0;
        #pragma unroll
        for (int e=0;e<NEXP;e++){
            loss += ((float)sc[e]*(1.0f/NTOK)) * (sexp[e]*(1.0f/NTOK));
            g_cnt[e]=sc[e]; g_off[e]=off; soff[e]=off; off+=sc[e];
        }
        g_loss += (float)NEXP*loss;
    }
    __syncthreads();
    for (int i=tid;i<RTOT;i+=1024){
        int e = g_topi[i];
        int r = soff[e] + atomicAdd(&scur[e], 1);
        g_row_tok[r] = i>>1;
        g_tok_row[i] = r;
    }
}

// ---------------- fp16x3 mma.sync grouped GEMM ----------------
#define APAD2 12
#define BPAD2 17
#define OFF_AH 0
#define OFF_AL 6144
#define OFF_BH 12288
#define OFF_BL 20992
#define BUF_SZ 29696
#define SM_TOTAL (512 + 2*BUF_SZ)

template<bool G1, int OCC>
__global__ void __launch_bounds__(256, OCC) moe_gemm_h3(const float* __restrict__ W,
                                                        const float* __restrict__ bias){
    constexpr int LDA = G1 ? DDIM : FDIM;
    constexpr int KT  = G1 ? DDIM : FDIM;
    constexpr int LDW = G1 ? FDIM : DDIM;
    constexpr int S   = KT/16;

    extern __shared__ char smem[];
    int* sidx = (int*)smem;
    char* bufbase = smem + 512;

    int e = blockIdx.z;
    int cnt = g_cnt[e];
    int m0 = blockIdx.y*128;
    if (m0 >= cnt) return;
    int off = g_off[e];
    int n0 = blockIdx.x*128;
    int tid = threadIdx.x, w = tid>>5, lane = tid&31;
    int g = lane>>2, tig = lane&3;
    int mw = (w&1)*64, nw = (w>>1)*32;

    const float* Asrc = G1 ? g_xn : g_H;
    float*       Out  = G1 ? g_H  : g_Y;

    if (tid < 128){
        int i = m0 + tid; if (i >= cnt) i = cnt-1;
        sidx[tid] = G1 ? g_row_tok[off+i] : (off+i);
    }
    __syncthreads();

    const float* aptr0 = Asrc + (size_t)sidx[tid>>2]*LDA + (tid&3)*4;
    const float* aptr1 = Asrc + (size_t)sidx[(tid>>2)+64]*LDA + (tid&3)*4;
    int kp = tid>>6;
    int n2 = (tid&63)*2;
    const float* bptr = W + (size_t)e*KT*LDW + n0 + n2;
    const float* biasp = bias + (size_t)e*LDW + n0;

    float4 av[2];
    float2 q00, q01, q10, q11;
    auto LOADS = [&](int s){
        int k0 = s*16;
        av[0] = *(const float4*)(aptr0 + k0);
        av[1] = *(const float4*)(aptr1 + k0);
        q00 = *(const float2*)(bptr + (size_t)(k0 + 2*kp    )*LDW);
        q01 = *(const float2*)(bptr + (size_t)(k0 + 2*kp + 1)*LDW);
        q10 = *(const float2*)(bptr + (size_t)(k0 + 2*kp + 8)*LDW);
        q11 = *(const float2*)(bptr + (size_t)(k0 + 2*kp + 9)*LDW);
    };
    auto STORES = [&](int b){
        char* bb = bufbase + b*BUF_SZ;
        uint32_t* Ah = (uint32_t*)(bb + OFF_AH);
        uint32_t* Al = (uint32_t*)(bb + OFF_AL);
        uint32_t* Bh = (uint32_t*)(bb + OFF_BH);
        uint32_t* Bl = (uint32_t*)(bb + OFF_BL);
        int kq = tid&3;
        #pragma unroll
        for (int i=0;i<2;i++){
            int row = (tid>>2) + 64*i;
            uint32_t h01,l01,h23,l23;
            split2(av[i].x, av[i].y, h01, l01);
            split2(av[i].z, av[i].w, h23, l23);
            int a = row*APAD2 + kq*2;
            *(uint2*)(Ah + a) = make_uint2(h01, h23);
            *(uint2*)(Al + a) = make_uint2(l01, l23);
        }
        {
            uint32_t h,l;
            split2(q00.x, q01.x, h, l); Bh[ n2   *BPAD2 + kp    ] = h; Bl[ n2   *BPAD2 + kp    ] = l;
            split2(q00.y, q01.y, h, l); Bh[(n2+1)*BPAD2 + kp    ] = h; Bl[(n2+1)*BPAD2 + kp    ] = l;
            split2(q10.x, q11.x, h, l); Bh[ n2   *BPAD2 + kp + 4] = h; Bl[ n2   *BPAD2 + kp + 4] = l;
            split2(q10.y, q11.y, h, l); Bh[(n2+1)*BPAD2 + kp + 4] = h; Bl[(n2+1)*BPAD2 + kp + 4] = l;
        }
    };

    float acc[4][4][4] = {};
    auto COMPUTE = [&](int b){
        char* bb = bufbase + b*BUF_SZ;
        const uint32_t* Ah = (const uint32_t*)(bb + OFF_AH);
        const uint32_t* Al = (const uint32_t*)(bb + OFF_AL);
        const uint32_t* Bh = (const uint32_t*)(bb + OFF_BH);
        const uint32_t* Bl = (const uint32_t*)(bb + OFF_BL);
        uint32_t afh[4][4], afl[4][4];
        #pragma unroll
        for (int mf=0;mf<4;mf++){
            int r0 = mw + mf*16 + g, r1 = r0 + 8;
            afh[mf][0] = Ah[r0*APAD2 + tig];
            afh[mf][1] = Ah[r1*APAD2 + tig];
            afh[mf][2] = Ah[r0*APAD2 + tig + 4];
            afh[mf][3] = Ah[r1*APAD2 + tig + 4];
            afl[mf][0] = Al[r0*APAD2 + tig];
            afl[mf][1] = Al[r1*APAD2 + tig];
            afl[mf][2] = Al[r0*APAD2 + tig + 4];
            afl[mf][3] = Al[r1*APAD2 + tig + 4];
        }
        #pragma unroll
        for (int nf=0;nf<4;nf++){
            int n = nw + nf*8 + g;
            uint32_t bh0 = Bh[n*BPAD2 + tig];
            uint32_t bh1 = Bh[n*BPAD2 + tig + 4];
            uint32_t bl0 = Bl[n*BPAD2 + tig];
            uint32_t bl1 = Bl[n*BPAD2 + tig + 4];
            #pragma unroll
            for (int mf=0;mf<4;mf++){
                mma16(acc[mf][nf], afh[mf], bh0, bh1);   // hi*hi
                mma16(acc[mf][nf], afl[mf], bh0, bh1);   // lo*hi
                mma16(acc[mf][nf], afh[mf], bl0, bl1);   // hi*lo
            }
        }
    };

    LOADS(0);
    STORES(0);
    __syncthreads();
    for (int s=0;s<S;s++){
        if (s+1 < S) LOADS(s+1);
        COMPUTE(s&1);
        if (s+1 < S){
            STORES((s+1)&1);
            __syncthreads();
        }
    }

    #pragma unroll
    for (int mf=0;mf<4;mf++){
        int r0 = m0 + mw + mf*16 + g;
        int r1 = r0 + 8;
        #pragma unroll
        for (int nf=0;nf<4;nf++){
            int col = nw + nf*8 + tig*2;
            float b0 = biasp[col], b1 = biasp[col+1];
            if (r0 < cnt){
                float2 o;
                o.x = acc[mf][nf][0] + b0;
                o.y = acc[mf][nf][1] + b1;
                if (G1){ o.x = gelu_tanh(o.x); o.y = gelu_tanh(o.y); }
                *(float2*)(Out + (size_t)(off+r0)*LDW + n0 + col) = o;
            }
            if (r1 < cnt){
                float2 o;
                o.x = acc[mf][nf][2] + b0;
                o.y = acc[mf][nf][3] + b1;
                if (G1){ o.x = gelu_tanh(o.x); o.y = gelu_tanh(o.y); }
                *(float2*)(Out + (size_t)(off+r1)*LDW + n0 + col) = o;
            }
        }
    }
}

// ---------------- combine ----------------
__global__ void combine_kernel(float* __restrict__ out){
    int t = blockIdx.x, tid = threadIdx.x;
    int r1 = g_tok_row[t*2+0], r2 = g_tok_row[t*2+1];
    float g1 = g_topv[t*2+0],  g2 = g_topv[t*2+1];
    const float* y1 = g_Y + (size_t)r1*DDIM;
    const float* y2 = g_Y + (size_t)r2*DDIM;
    #pragma unroll
    for (int q=0;q<4;q++){
        int d = q*256 + tid;
        out[(size_t)t*DDIM + d] += g1*y1[d] + g2*y2[d];
    }
}
__global__ void finish_kernel(float* __restrict__ out){
    out[(size_t)NTOK*DDIM] = g_loss;
}

// ================= exact-recompute path (bitwise-R1 for flagged tokens) =================
__global__ void flist_kernel(){
    int t = blockIdx.x*blockDim.x + threadIdx.x;
    if (t < NTOK && g_flag[t]){
        int pos = atomicAdd(&g_F, 1);
        if (pos < MAXF) g_flist[pos] = t;
    }
}
__global__ void ex_init_kernel(const float* __restrict__ x){
    int b = blockIdx.x;
    if (b >= g_F || b >= MAXF) return;
    int t = g_flist[b], tid = threadIdx.x;
    #pragma unroll
    for (int q=0;q<4;q++)
        ex_x[b*DDIM + q*256 + tid] = x[(size_t)t*DDIM + q*256 + tid];
}
__global__ void ex_ln_kernel(){
    int b = blockIdx.x;
    if (b >= g_F || b >= MAXF) return;
    int tid = threadIdx.x;
    __shared__ float red[256];
    float v[4];
    #pragma unroll
    for (int q=0;q<4;q++) v[q] = ex_x[b*DDIM + q*256 + tid];
    float s = v[0]+v[1]+v[2]+v[3];
    red[tid]=s; __syncthreads();
    for (int o=128;o>0;o>>=1){ if(tid<o) red[tid]+=red[tid+o]; __syncthreads(); }
    float mean = red[0]*(1.0f/DDIM);
    __syncthreads();
    float s2=0.f;
    #pragma unroll
    for (int q=0;q<4;q++){ v[q]-=mean; s2 += v[q]*v[q]; }
    red[tid]=s2; __syncthreads();
    for (int o=128;o>0;o>>=1){ if(tid<o) red[tid]+=red[tid+o]; __syncthreads(); }
    float inv = 1.0f/sqrtf(red[0]*(1.0f/DDIM) + 1e-5f);
    #pragma unroll
    for (int q=0;q<4;q++) ex_xn[b*DDIM + q*256 + tid] = v[q]*inv;
}
__global__ void ex_router_kernel(const float* __restrict__ wr){
    int b = blockIdx.x;
    if (b >= g_F || b >= MAXF) return;
    int tid = threadIdx.x;
    __shared__ float sx[DDIM];
    __shared__ float slog[NEXP];
    #pragma unroll
    for (int q=0;q<4;q++) sx[q*256+tid] = ex_xn[b*DDIM + q*256 + tid];
    __syncthreads();
    int e = tid>>5, lane = tid&31;
    float acc = 0.f;
    for (int d=lane; d<DDIM; d+=32) acc += sx[d]*wr[d*NEXP+e];
    #pragma unroll
    for (int o=16;o>0;o>>=1) acc += __shfl_down_sync(0xffffffffu, acc, o);
    if (lane==0) slog[e]=acc;
    __syncthreads();
    if (tid==0){
        float p[NEXP];
        float m = slog[0];
        #pragma unroll
        for (int i=1;i<NEXP;i++) m = fmaxf(m, slog[i]);
        float ssum = 0.f;
        #pragma unroll
        for (int i=0;i<NEXP;i++){ p[i]=expf(slog[i]-m); ssum+=p[i]; }
        #pragma unroll
        for (int i=0;i<NEXP;i++) p[i] = p[i]/ssum;
        int i1=0; float v1=p[0];
        #pragma unroll
        for (int i=1;i<NEXP;i++) if (p[i]>v1){ v1=p[i]; i1=i; }
        int i2=-1; float v2=-1e30f;
        #pragma unroll
        for (int i=0;i<NEXP;i++) if (i!=i1 && p[i]>v2){ v2=p[i]; i2=i; }
        ex_topi[b*2+0]=i1; ex_topv[b*2+0]=v1;
        ex_topi[b*2+1]=i2; ex_topv[b*2+1]=v2;
    }
}
__global__ void ex_gemm1_kernel(const float* __restrict__ w1l, const float* __restrict__ b1l){
    int b = blockIdx.z;
    if (b >= g_F || b >= MAXF) return;
    int slot = blockIdx.y, tid = threadIdx.x;
    int col = blockIdx.x*256 + tid;
    int e = ex_topi[b*2+slot];
    __shared__ float sxn[DDIM];
    #pragma unroll
    for (int q=0;q<4;q++) sxn[q*256+tid] = ex_xn[b*DDIM + q*256 + tid];
    __syncthreads();
    const float* wcol = w1l + (size_t)e*DDIM*FDIM + col;
    float acc = 0.f;
    #pragma unroll 8
    for (int k=0;k<DDIM;k++) acc = fmaf(sxn[k], wcol[(size_t)k*FDIM], acc);
    float bb = b1l[(size_t)e*FDIM + col];
    ex_h[((size_t)b*2+slot)*FDIM + col] = gelu_tanh(acc + bb);
}
__global__ void ex_gemm2_kernel(const float* __restrict__ w2l, const float* __restrict__ b2l){
    int b = blockIdx.z;
    if (b >= g_F || b >= MAXF) return;
    int slot = blockIdx.y, tid = threadIdx.x;
    int col = blockIdx.x*256 + tid;
    int e = ex_topi[b*2+slot];
    __shared__ float sh[FDIM];
    #pragma unroll
    for (int q=0;q<16;q++) sh[q*256+tid] = ex_h[((size_t)b*2+slot)*FDIM + q*256 + tid];
    __syncthreads();
    const float* wcol = w2l + (size_t)e*FDIM*DDIM + col;
    float acc = 0.f;
    #pragma unroll 8
    for (int k=0;k<FDIM;k++) acc = fmaf(sh[k], wcol[(size_t)k*DDIM], acc);
    float bb = b2l[(size_t)e*DDIM + col];
    ex_y[((size_t)b*2+slot)*DDIM + col] = acc + bb;
}
__global__ void ex_combine_kernel(){
    int b = blockIdx.x;
    if (b >= g_F || b >= MAXF) return;
    int tid = threadIdx.x;
    float g1 = ex_topv[b*2+0], g2 = ex_topv[b*2+1];
    const float* y1 = ex_y + ((size_t)b*2+0)*DDIM;
    const float* y2 = ex_y + ((size_t)b*2+1)*DDIM;
    #pragma unroll
    for (int q=0;q<4;q++){
        int d = q*256 + tid;
        ex_x[b*DDIM + d] += g1*y1[d] + g2*y2[d];
    }
}
__global__ void ex_write_kernel(float* __restrict__ out){
    int b = blockIdx.x;
    if (b >= g_F || b >= MAXF) return;
    int t = g_flist[b], tid = threadIdx.x;
    #pragma unroll
    for (int q=0;q<4;q++)
        out[(size_t)t*DDIM + q*256 + tid] = ex_x[b*DDIM + q*256 + tid];
}

// ---------------- launch ----------------
extern "C" void kernel_launch(void* const* d_in, const int* in_sizes, int n_in,
                              void* d_out, int out_size){
    const float* x  = (const float*)d_in[0];
    const float* wr = (const float*)d_in[1];
    const float* w1 = (const float*)d_in[2];
    const float* b1 = (const float*)d_in[3];
    const float* w2 = (const float*)d_in[4];
    const float* b2 = (const float*)d_in[5];
    float* out = (float*)d_out;

    cudaFuncSetAttribute((const void*)moe_gemm_h3<true,2>,  cudaFuncAttributeMaxDynamicSharedMemorySize, SM_TOTAL);
    cudaFuncSetAttribute((const void*)moe_gemm_h3<false,2>, cudaFuncAttributeMaxDynamicSharedMemorySize, SM_TOTAL);

    init_kernel<<<NTOK, 1024>>>(x, out);

    // fast path (launch #4 == moe_gemm_h3<true,2> for ncu capture)
    for (int l=0;l<NLAY;l++){
        const float* wr_l = wr + (size_t)l*DDIM*NEXP;
        const float* w1_l = w1 + (size_t)l*NEXP*DDIM*FDIM;
        const float* b1_l = b1 + (size_t)l*NEXP*FDIM;
        const float* w2_l = w2 + (size_t)l*NEXP*FDIM*DDIM;
        const float* b2_l = b2 + (size_t)l*NEXP*DDIM;

        lnrouter_kernel  <<<NTOK, 256>>>(out, wr_l);
        statsplace_kernel<<<1, 1024>>>();
        moe_gemm_h3<true,2> <<<dim3(FDIM/128, 32, NEXP), 256, SM_TOTAL>>>(w1_l, b1_l);
        moe_gemm_h3<false,2><<<dim3(DDIM/128, 32, NEXP), 256, SM_TOTAL>>>(w2_l, b2_l);
        combine_kernel<<<NTOK, 256>>>(out);
    }

    // exact recompute of flagged tokens (bitwise-R1, R10 structure — measured good)
    flist_kernel  <<<NTOK/256, 256>>>();
    ex_init_kernel<<<MAXF, 256>>>(x);
    for (int l=0;l<NLAY;l++){
        const float* wr_l = wr + (size_t)l*DDIM*NEXP;
        const float* w1_l = w1 + (size_t)l*NEXP*DDIM*FDIM;
        const float* b1_l = b1 + (size_t)l*NEXP*FDIM;
        const float* w2_l = w2 + (size_t)l*NEXP*FDIM*DDIM;
        const float* b2_l = b2 + (size_t)l*NEXP*DDIM;

        ex_ln_kernel    <<<MAXF, 256>>>();
        ex_router_kernel<<<MAXF, 256>>>(wr_l);
        ex_gemm1_kernel <<<dim3(FDIM/256, 2, MAXF), 256>>>(w1_l, b1_l);
        ex_gemm2_kernel <<<dim3(DDIM/256, 2, MAXF), 256>>>(w2_l, b2_l);
        ex_combine_kernel<<<MAXF, 256>>>();
    }
    ex_write_kernel<<<MAXF, 256>>>(out);

    if (out_size > NTOK*DDIM) finish_kernel<<<1,1>>>(out);
}

// round 13
// speedup vs baseline: 2.3037x; 1.0064x over previous
#include <cuda_runtime.h>
#include <cuda_fp16.h>
#include <math.h>
#include <stdint.h>

#define NTOK 2048
#define DDIM 1024
#define FDIM 4096
#define NEXP 8
#define NLAY 6
#define RTOT (NTOK*2)
#define MAXF 256
#define TAU  2e-4f
#define KSPL 4

// ---------------- scratch ----------------
__device__ float g_xn[NTOK*DDIM];
__device__ float g_probs[NTOK*NEXP];
__device__ int   g_topi[RTOT];
__device__ float g_topv[RTOT];
__device__ int   g_cnt[NEXP], g_off[NEXP];
__device__ int   g_row_tok[RTOT];
__device__ int   g_tok_row[RTOT];
__device__ float g_H[(size_t)RTOT*FDIM];
__device__ float g_Yp[(size_t)KSPL*RTOT*DDIM];   // split-K partials for GEMM2
__device__ float g_loss;
// exact-recompute scratch
__device__ int   g_flag[NTOK];
__device__ int   g_flist[MAXF];
__device__ int   g_F;
__device__ float ex_x [MAXF*DDIM];
__device__ float ex_xn[MAXF*DDIM];
__device__ float ex_h [(size_t)MAXF*2*FDIM];
__device__ float ex_y [(size_t)MAXF*2*DDIM];
__device__ int   ex_topi[MAXF*2];
__device__ float ex_topv[MAXF*2];

__device__ __forceinline__ void mma16(float* d, const uint32_t* a, uint32_t b0, uint32_t b1){
    asm volatile("mma.sync.aligned.m16n8k16.row.col.f32.f16.f16.f32 "
        "{%0,%1,%2,%3}, {%4,%5,%6,%7}, {%8,%9}, {%0,%1,%2,%3};"
        : "+f"(d[0]), "+f"(d[1]), "+f"(d[2]), "+f"(d[3])
        : "r"(a[0]), "r"(a[1]), "r"(a[2]), "r"(a[3]), "r"(b0), "r"(b1));
}
__device__ __forceinline__ void split2(float x, float y, uint32_t& hi, uint32_t& lo){
    __half2 h = __floats2half2_rn(x, y);
    float hx = __low2float(h), hy = __high2float(h);
    __half2 l = __floats2half2_rn(x - hx, y - hy);
    hi = *reinterpret_cast<uint32_t*>(&h);
    lo = *reinterpret_cast<uint32_t*>(&l);
}
__device__ __forceinline__ float gelu_tanh(float x){
    float x3 = x*x*x;
    float t  = tanhf(0.7978845608028654f*(x + 0.044715f*x3));
    return 0.5f*x*(1.0f+t);
}

// ---------------- init ----------------
__global__ void init_kernel(const float* __restrict__ x, float* __restrict__ out){
    int i = blockIdx.x*blockDim.x + threadIdx.x;
    out[i] = x[i];
    if (i < NTOK) g_flag[i] = 0;
    if (i == 0){ g_loss = 0.0f; g_F = 0; }
}

// ---------------- fused LN + router (fast path, with margin flag) ----------------
__global__ void lnrouter_kernel(const float* __restrict__ xin, const float* __restrict__ wr){
    int t = blockIdx.x, tid = threadIdx.x;
    __shared__ float red[256];
    __shared__ float sx[DDIM];
    __shared__ float slog[NEXP];
    float v[4];
    #pragma unroll
    for (int q=0;q<4;q++) v[q] = xin[(size_t)t*DDIM + q*256 + tid];
    float s = v[0]+v[1]+v[2]+v[3];
    red[tid]=s; __syncthreads();
    for (int o=128;o>0;o>>=1){ if(tid<o) red[tid]+=red[tid+o]; __syncthreads(); }
    float mean = red[0]*(1.0f/DDIM);
    __syncthreads();
    float s2=0.f;
    #pragma unroll
    for (int q=0;q<4;q++){ v[q]-=mean; s2 += v[q]*v[q]; }
    red[tid]=s2; __syncthreads();
    for (int o=128;o>0;o>>=1){ if(tid<o) red[tid]+=red[tid+o]; __syncthreads(); }
    float inv = 1.0f/sqrtf(red[0]*(1.0f/DDIM) + 1e-5f);
    #pragma unroll
    for (int q=0;q<4;q++){
        float nv = v[q]*inv;
        g_xn[(size_t)t*DDIM + q*256 + tid] = nv;
        sx[q*256 + tid] = nv;
    }
    __syncthreads();
    int e = tid>>5, lane = tid&31;
    float acc = 0.f;
    for (int d=lane; d<DDIM; d+=32) acc += sx[d]*wr[d*NEXP+e];
    #pragma unroll
    for (int o=16;o>0;o>>=1) acc += __shfl_down_sync(0xffffffffu, acc, o);
    if (lane==0) slog[e]=acc;
    __syncthreads();
    if (tid==0){
        float p[NEXP];
        float m = slog[0];
        #pragma unroll
        for (int i=1;i<NEXP;i++) m = fmaxf(m, slog[i]);
        float ssum = 0.f;
        #pragma unroll
        for (int i=0;i<NEXP;i++){ p[i]=expf(slog[i]-m); ssum+=p[i]; }
        #pragma unroll
        for (int i=0;i<NEXP;i++){ p[i] = p[i]/ssum; g_probs[t*NEXP+i]=p[i]; }
        int i1=0; float v1=p[0];
        #pragma unroll
        for (int i=1;i<NEXP;i++) if (p[i]>v1){ v1=p[i]; i1=i; }
        int i2=-1; float v2=-1e30f;
        #pragma unroll
        for (int i=0;i<NEXP;i++) if (i!=i1 && p[i]>v2){ v2=p[i]; i2=i; }
        float v3=-1e30f;
        #pragma unroll
        for (int i=0;i<NEXP;i++) if (i!=i1 && i!=i2 && p[i]>v3) v3=p[i];
        if (v2 - v3 < TAU) g_flag[t] = 1;
        g_topi[t*2+0]=i1; g_topv[t*2+0]=v1;
        g_topi[t*2+1]=i2; g_topv[t*2+1]=v2;
    }
}

// ---------------- stats + placement (single block) ----------------
__global__ void statsplace_kernel(){
    int tid = threadIdx.x;                 // 1024 threads
    __shared__ int   sc[NEXP];
    __shared__ int   scur[NEXP];
    __shared__ int   soff[NEXP];
    __shared__ float red[1024];
    __shared__ float sexp[NEXP];
    if (tid<NEXP){ sc[tid]=0; scur[tid]=0; }
    __syncthreads();
    for (int i=tid;i<RTOT;i+=1024) atomicAdd(&sc[g_topi[i]], 1);
    float myp[NEXP];
    #pragma unroll
    for (int e=0;e<NEXP;e++) myp[e]=0.f;
    for (int t=tid;t<NTOK;t+=1024){
        #pragma unroll
        for (int e=0;e<NEXP;e++) myp[e] += g_probs[t*NEXP+e];
    }
    __syncthreads();
    for (int e=0;e<NEXP;e++){
        red[tid]=myp[e]; __syncthreads();
        for (int o=512;o>0;o>>=1){ if(tid<o) red[tid]+=red[tid+o]; __syncthreads(); }
        if (tid==0) sexp[e]=red[0];
        __syncthreads();
    }
    if (tid==0){
        float loss=0.f; int off=0;
        #pragma unroll
        for (int e=0;e<NEXP;e++){
            loss += ((float)sc[e]*(1.0f/NTOK)) * (sexp[e]*(1.0f/NTOK));
            g_cnt[e]=sc[e]; g_off[e]=off; soff[e]=off; off+=sc[e];
        }
        g_loss += (float)NEXP*loss;
    }
    __syncthreads();
    for (int i=tid;i<RTOT;i+=1024){
        int e = g_topi[i];
        int r = soff[e] + atomicAdd(&scur[e], 1);
        g_row_tok[r] = i>>1;
        g_tok_row[i] = r;
    }
}

// ---------------- fp16x3 mma.sync grouped GEMM (optional split-K) ----------------
#define APAD2 12
#define BPAD2 17
#define OFF_AH 0
#define OFF_AL 6144
#define OFF_BH 12288
#define OFF_BL 20992
#define BUF_SZ 29696
#define SM_TOTAL (512 + 2*BUF_SZ)

template<bool G1, int OCC, int KSP>
__global__ void __launch_bounds__(256, OCC) moe_gemm_h3(const float* __restrict__ W,
                                                        const float* __restrict__ bias){
    constexpr int LDA = G1 ? DDIM : FDIM;
    constexpr int KT  = G1 ? DDIM : FDIM;
    constexpr int LDW = G1 ? FDIM : DDIM;
    constexpr int S   = KT/16/KSP;          // stages in this CTA's K chunk

    extern __shared__ char smem[];
    int* sidx = (int*)smem;
    char* bufbase = smem + 512;

    int e = blockIdx.z;
    int cnt = g_cnt[e];
    int ks = 0, my = blockIdx.y;
    if (KSP > 1){ ks = my & (KSP-1); my >>= 2; }
    int m0 = my*128;
    if (m0 >= cnt) return;
    int off = g_off[e];
    int n0 = blockIdx.x*128;
    int kbase = ks*(KT/KSP);
    int tid = threadIdx.x, w = tid>>5, lane = tid&31;
    int g = lane>>2, tig = lane&3;
    int mw = (w&1)*64, nw = (w>>1)*32;

    const float* Asrc = G1 ? g_xn : g_H;
    float*       Out  = G1 ? g_H  : (g_Yp + (size_t)ks*RTOT*DDIM);

    if (tid < 128){
        int i = m0 + tid; if (i >= cnt) i = cnt-1;
        sidx[tid] = G1 ? g_row_tok[off+i] : (off+i);
    }
    __syncthreads();

    const float* aptr0 = Asrc + (size_t)sidx[tid>>2]*LDA + kbase + (tid&3)*4;
    const float* aptr1 = Asrc + (size_t)sidx[(tid>>2)+64]*LDA + kbase + (tid&3)*4;
    int kp = tid>>6;
    int n2 = (tid&63)*2;
    const float* bptr = W + (size_t)e*KT*LDW + (size_t)kbase*LDW + n0 + n2;
    const float* biasp = bias + (size_t)e*LDW + n0;

    float4 av[2];
    float2 q00, q01, q10, q11;
    auto LOADS = [&](int s){
        int k0 = s*16;
        av[0] = *(const float4*)(aptr0 + k0);
        av[1] = *(const float4*)(aptr1 + k0);
        q00 = *(const float2*)(bptr + (size_t)(k0 + 2*kp    )*LDW);
        q01 = *(const float2*)(bptr + (size_t)(k0 + 2*kp + 1)*LDW);
        q10 = *(const float2*)(bptr + (size_t)(k0 + 2*kp + 8)*LDW);
        q11 = *(const float2*)(bptr + (size_t)(k0 + 2*kp + 9)*LDW);
    };
    auto STORES = [&](int b){
        char* bb = bufbase + b*BUF_SZ;
        uint32_t* Ah = (uint32_t*)(bb + OFF_AH);
        uint32_t* Al = (uint32_t*)(bb + OFF_AL);
        uint32_t* Bh = (uint32_t*)(bb + OFF_BH);
        uint32_t* Bl = (uint32_t*)(bb + OFF_BL);
        int kq = tid&3;
        #pragma unroll
        for (int i=0;i<2;i++){
            int row = (tid>>2) + 64*i;
            uint32_t h01,l01,h23,l23;
            split2(av[i].x, av[i].y, h01, l01);
            split2(av[i].z, av[i].w, h23, l23);
            int a = row*APAD2 + kq*2;
            *(uint2*)(Ah + a) = make_uint2(h01, h23);
            *(uint2*)(Al + a) = make_uint2(l01, l23);
        }
        {
            uint32_t h,l;
            split2(q00.x, q01.x, h, l); Bh[ n2   *BPAD2 + kp    ] = h; Bl[ n2   *BPAD2 + kp    ] = l;
            split2(q00.y, q01.y, h, l); Bh[(n2+1)*BPAD2 + kp    ] = h; Bl[(n2+1)*BPAD2 + kp    ] = l;
            split2(q10.x, q11.x, h, l); Bh[ n2   *BPAD2 + kp + 4] = h; Bl[ n2   *BPAD2 + kp + 4] = l;
            split2(q10.y, q11.y, h, l); Bh[(n2+1)*BPAD2 + kp + 4] = h; Bl[(n2+1)*BPAD2 + kp + 4] = l;
        }
    };

    float acc[4][4][4] = {};
    auto COMPUTE = [&](int b){
        char* bb = bufbase + b*BUF_SZ;
        const uint32_t* Ah = (const uint32_t*)(bb + OFF_AH);
        const uint32_t* Al = (const uint32_t*)(bb + OFF_AL);
        const uint32_t* Bh = (const uint32_t*)(bb + OFF_BH);
        const uint32_t* Bl = (const uint32_t*)(bb + OFF_BL);
        uint32_t afh[4][4], afl[4][4];
        #pragma unroll
        for (int mf=0;mf<4;mf++){
            int r0 = mw + mf*16 + g, r1 = r0 + 8;
            afh[mf][0] = Ah[r0*APAD2 + tig];
            afh[mf][1] = Ah[r1*APAD2 + tig];
            afh[mf][2] = Ah[r0*APAD2 + tig + 4];
            afh[mf][3] = Ah[r1*APAD2 + tig + 4];
            afl[mf][0] = Al[r0*APAD2 + tig];
            afl[mf][1] = Al[r1*APAD2 + tig];
            afl[mf][2] = Al[r0*APAD2 + tig + 4];
            afl[mf][3] = Al[r1*APAD2 + tig + 4];
        }
        #pragma unroll
        for (int nf=0;nf<4;nf++){
            int n = nw + nf*8 + g;
            uint32_t bh0 = Bh[n*BPAD2 + tig];
            uint32_t bh1 = Bh[n*BPAD2 + tig + 4];
            uint32_t bl0 = Bl[n*BPAD2 + tig];
            uint32_t bl1 = Bl[n*BPAD2 + tig + 4];
            #pragma unroll
            for (int mf=0;mf<4;mf++){
                mma16(acc[mf][nf], afh[mf], bh0, bh1);   // hi*hi
                mma16(acc[mf][nf], afl[mf], bh0, bh1);   // lo*hi
                mma16(acc[mf][nf], afh[mf], bl0, bl1);   // hi*lo
            }
        }
    };

    LOADS(0);
    STORES(0);
    __syncthreads();
    for (int s=0;s<S;s++){
        if (s+1 < S) LOADS(s+1);
        COMPUTE(s&1);
        if (s+1 < S){
            STORES((s+1)&1);
            __syncthreads();
        }
    }

    #pragma unroll
    for (int mf=0;mf<4;mf++){
        int r0 = m0 + mw + mf*16 + g;
        int r1 = r0 + 8;
        #pragma unroll
        for (int nf=0;nf<4;nf++){
            int col = nw + nf*8 + tig*2;
            float b0 = (KSP==1) ? biasp[col]   : 0.f;
            float b1 = (KSP==1) ? biasp[col+1] : 0.f;
            if (r0 < cnt){
                float2 o;
                o.x = acc[mf][nf][0] + b0;
                o.y = acc[mf][nf][1] + b1;
                if (G1){ o.x = gelu_tanh(o.x); o.y = gelu_tanh(o.y); }
                *(float2*)(Out + (size_t)(off+r0)*LDW + n0 + col) = o;
            }
            if (r1 < cnt){
                float2 o;
                o.x = acc[mf][nf][2] + b0;
                o.y = acc[mf][nf][3] + b1;
                if (G1){ o.x = gelu_tanh(o.x); o.y = gelu_tanh(o.y); }
                *(float2*)(Out + (size_t)(off+r1)*LDW + n0 + col) = o;
            }
        }
    }
}

// ---------------- combine: fuse split-K reduction + bias + gated residual ----------------
__global__ void combine_kernel(float* __restrict__ out, const float* __restrict__ b2l){
    int t = blockIdx.x, tid = threadIdx.x;
    int r1 = g_tok_row[t*2+0], r2 = g_tok_row[t*2+1];
    float g1 = g_topv[t*2+0],  g2 = g_topv[t*2+1];
    int e1 = g_topi[t*2+0],    e2 = g_topi[t*2+1];
    const float* p0 = g_Yp;
    #pragma unroll
    for (int q=0;q<4;q++){
        int d = q*256 + tid;
        float y1 = p0[((size_t)0*RTOT + r1)*DDIM + d]
                 + p0[((size_t)1*RTOT + r1)*DDIM + d]
                 + p0[((size_t)2*RTOT + r1)*DDIM + d]
                 + p0[((size_t)3*RTOT + r1)*DDIM + d]
                 + b2l[(size_t)e1*DDIM + d];
        float y2 = p0[((size_t)0*RTOT + r2)*DDIM + d]
                 + p0[((size_t)1*RTOT + r2)*DDIM + d]
                 + p0[((size_t)2*RTOT + r2)*DDIM + d]
                 + p0[((size_t)3*RTOT + r2)*DDIM + d]
                 + b2l[(size_t)e2*DDIM + d];
        out[(size_t)t*DDIM + d] += g1*y1 + g2*y2;
    }
}
__global__ void finish_kernel(float* __restrict__ out){
    out[(size_t)NTOK*DDIM] = g_loss;
}

// ================= exact-recompute path (bitwise-R1 for flagged tokens) =================
__global__ void flist_kernel(){
    int t = blockIdx.x*blockDim.x + threadIdx.x;
    if (t < NTOK && g_flag[t]){
        int pos = atomicAdd(&g_F, 1);
        if (pos < MAXF) g_flist[pos] = t;
    }
}
__global__ void ex_init_kernel(const float* __restrict__ x){
    int b = blockIdx.x;
    if (b >= g_F || b >= MAXF) return;
    int t = g_flist[b], tid = threadIdx.x;
    #pragma unroll
    for (int q=0;q<4;q++)
        ex_x[b*DDIM + q*256 + tid] = x[(size_t)t*DDIM + q*256 + tid];
}
__global__ void ex_ln_kernel(){
    int b = blockIdx.x;
    if (b >= g_F || b >= MAXF) return;
    int tid = threadIdx.x;
    __shared__ float red[256];
    float v[4];
    #pragma unroll
    for (int q=0;q<4;q++) v[q] = ex_x[b*DDIM + q*256 + tid];
    float s = v[0]+v[1]+v[2]+v[3];
    red[tid]=s; __syncthreads();
    for (int o=128;o>0;o>>=1){ if(tid<o) red[tid]+=red[tid+o]; __syncthreads(); }
    float mean = red[0]*(1.0f/DDIM);
    __syncthreads();
    float s2=0.f;
    #pragma unroll
    for (int q=0;q<4;q++){ v[q]-=mean; s2 += v[q]*v[q]; }
    red[tid]=s2; __syncthreads();
    for (int o=128;o>0;o>>=1){ if(tid<o) red[tid]+=red[tid+o]; __syncthreads(); }
    float inv = 1.0f/sqrtf(red[0]*(1.0f/DDIM) + 1e-5f);
    #pragma unroll
    for (int q=0;q<4;q++) ex_xn[b*DDIM + q*256 + tid] = v[q]*inv;
}
__global__ void ex_router_kernel(const float* __restrict__ wr){
    int b = blockIdx.x;
    if (b >= g_F || b >= MAXF) return;
    int tid = threadIdx.x;
    __shared__ float sx[DDIM];
    __shared__ float slog[NEXP];
    #pragma unroll
    for (int q=0;q<4;q++) sx[q*256+tid] = ex_xn[b*DDIM + q*256 + tid];
    __syncthreads();
    int e = tid>>5, lane = tid&31;
    float acc = 0.f;
    for (int d=lane; d<DDIM; d+=32) acc += sx[d]*wr[d*NEXP+e];
    #pragma unroll
    for (int o=16;o>0;o>>=1) acc += __shfl_down_sync(0xffffffffu, acc, o);
    if (lane==0) slog[e]=acc;
    __syncthreads();
    if (tid==0){
        float p[NEXP];
        float m = slog[0];
        #pragma unroll
        for (int i=1;i<NEXP;i++) m = fmaxf(m, slog[i]);
        float ssum = 0.f;
        #pragma unroll
        for (int i=0;i<NEXP;i++){ p[i]=expf(slog[i]-m); ssum+=p[i]; }
        #pragma unroll
        for (int i=0;i<NEXP;i++) p[i] = p[i]/ssum;
        int i1=0; float v1=p[0];
        #pragma unroll
        for (int i=1;i<NEXP;i++) if (p[i]>v1){ v1=p[i]; i1=i; }
        int i2=-1; float v2=-1e30f;
        #pragma unroll
        for (int i=0;i<NEXP;i++) if (i!=i1 && p[i]>v2){ v2=p[i]; i2=i; }
        ex_topi[b*2+0]=i1; ex_topv[b*2+0]=v1;
        ex_topi[b*2+1]=i2; ex_topv[b*2+1]=v2;
    }
}
__global__ void ex_gemm1_kernel(const float* __restrict__ w1l, const float* __restrict__ b1l){
    int b = blockIdx.z;
    if (b >= g_F || b >= MAXF) return;
    int slot = blockIdx.y, tid = threadIdx.x;
    int col = blockIdx.x*256 + tid;
    int e = ex_topi[b*2+slot];
    __shared__ float sxn[DDIM];
    #pragma unroll
    for (int q=0;q<4;q++) sxn[q*256+tid] = ex_xn[b*DDIM + q*256 + tid];
    __syncthreads();
    const float* wcol = w1l + (size_t)e*DDIM*FDIM + col;
    float acc = 0.f;
    #pragma unroll 8
    for (int k=0;k<DDIM;k++) acc = fmaf(sxn[k], wcol[(size_t)k*FDIM], acc);
    float bb = b1l[(size_t)e*FDIM + col];
    ex_h[((size_t)b*2+slot)*FDIM + col] = gelu_tanh(acc + bb);
}
__global__ void ex_gemm2_kernel(const float* __restrict__ w2l, const float* __restrict__ b2l){
    int b = blockIdx.z;
    if (b >= g_F || b >= MAXF) return;
    int slot = blockIdx.y, tid = threadIdx.x;
    int col = blockIdx.x*256 + tid;
    int e = ex_topi[b*2+slot];
    __shared__ float sh[FDIM];
    #pragma unroll
    for (int q=0;q<16;q++) sh[q*256+tid] = ex_h[((size_t)b*2+slot)*FDIM + q*256 + tid];
    __syncthreads();
    const float* wcol = w2l + (size_t)e*FDIM*DDIM + col;
    float acc = 0.f;
    #pragma unroll 8
    for (int k=0;k<FDIM;k++) acc = fmaf(sh[k], wcol[(size_t)k*DDIM], acc);
    float bb = b2l[(size_t)e*DDIM + col];
    ex_y[((size_t)b*2+slot)*DDIM + col] = acc + bb;
}
__global__ void ex_combine_kernel(){
    int b = blockIdx.x;
    if (b >= g_F || b >= MAXF) return;
    int tid = threadIdx.x;
    float g1 = ex_topv[b*2+0], g2 = ex_topv[b*2+1];
    const float* y1 = ex_y + ((size_t)b*2+0)*DDIM;
    const float* y2 = ex_y + ((size_t)b*2+1)*DDIM;
    #pragma unroll
    for (int q=0;q<4;q++){
        int d = q*256 + tid;
        ex_x[b*DDIM + d] += g1*y1[d] + g2*y2[d];
    }
}
__global__ void ex_write_kernel(float* __restrict__ out){
    int b = blockIdx.x;
    if (b >= g_F || b >= MAXF) return;
    int t = g_flist[b], tid = threadIdx.x;
    #pragma unroll
    for (int q=0;q<4;q++)
        out[(size_t)t*DDIM + q*256 + tid] = ex_x[b*DDIM + q*256 + tid];
}

// ---------------- launch ----------------
extern "C" void kernel_launch(void* const* d_in, const int* in_sizes, int n_in,
                              void* d_out, int out_size){
    const float* x  = (const float*)d_in[0];
    const float* wr = (const float*)d_in[1];
    const float* w1 = (const float*)d_in[2];
    const float* b1 = (const float*)d_in[3];
    const float* w2 = (const float*)d_in[4];
    const float* b2 = (const float*)d_in[5];
    float* out = (float*)d_out;

    cudaFuncSetAttribute((const void*)moe_gemm_h3<true,2,1>,  cudaFuncAttributeMaxDynamicSharedMemorySize, SM_TOTAL);
    cudaFuncSetAttribute((const void*)moe_gemm_h3<false,2,KSPL>, cudaFuncAttributeMaxDynamicSharedMemorySize, SM_TOTAL);

    init_kernel<<<NTOK, 1024>>>(x, out);

    // fast path (launch #4 == moe_gemm_h3<true,2,1> for ncu capture)
    for (int l=0;l<NLAY;l++){
        const float* wr_l = wr + (size_t)l*DDIM*NEXP;
        const float* w1_l = w1 + (size_t)l*NEXP*DDIM*FDIM;
        const float* b1_l = b1 + (size_t)l*NEXP*FDIM;
        const float* w2_l = w2 + (size_t)l*NEXP*FDIM*DDIM;
        const float* b2_l = b2 + (size_t)l*NEXP*DDIM;

        lnrouter_kernel  <<<NTOK, 256>>>(out, wr_l);
        statsplace_kernel<<<1, 1024>>>();
        moe_gemm_h3<true,2,1> <<<dim3(FDIM/128, 32, NEXP), 256, SM_TOTAL>>>(w1_l, b1_l);
        moe_gemm_h3<false,2,KSPL><<<dim3(DDIM/128, 32*KSPL, NEXP), 256, SM_TOTAL>>>(w2_l, b2_l);
        combine_kernel<<<NTOK, 256>>>(out, b2_l);
    }

    // exact recompute of flagged tokens (bitwise-R1, R10 structure — measured good)
    flist_kernel  <<<NTOK/256, 256>>>();
    ex_init_kernel<<<MAXF, 256>>>(x);
    for (int l=0;l<NLAY;l++){
        const float* wr_l = wr + (size_t)l*DDIM*NEXP;
        const float* w1_l = w1 + (size_t)l*NEXP*DDIM*FDIM;
        const float* b1_l = b1 + (size_t)l*NEXP*FDIM;
        const float* w2_l = w2 + (size_t)l*NEXP*FDIM*DDIM;
        const float* b2_l = b2 + (size_t)l*NEXP*DDIM;

        ex_ln_kernel    <<<MAXF, 256>>>();
        ex_router_kernel<<<MAXF, 256>>>(wr_l);
        ex_gemm1_kernel <<<dim3(FDIM/256, 2, MAXF), 256>>>(w1_l, b1_l);
        ex_gemm2_kernel <<<dim3(DDIM/256, 2, MAXF), 256>>>(w2_l, b2_l);
        ex_combine_kernel<<<MAXF, 256>>>();
    }
    ex_write_kernel<<<MAXF, 256>>>(out);

    if (out_size > NTOK*DDIM) finish_kernel<<<1,1>>>(out);
}